// round 1
// baseline (speedup 1.0000x reference)
#include <cuda_runtime.h>
#include <math.h>

#define NQ 50
#define NS 64
#define NP 3
#define BN 128   // n-rows per block

typedef unsigned long long u64;

// Precomputed head tables (device globals: no allocation allowed)
__device__ float g_h0[NQ * NS];   // H0[q][s] = sp0/sum  (layout q-major, s contiguous)
__device__ float g_h1[NQ * NS];   // H1[q][s] = sp1/sum
__device__ float g_hr[NS];        // hr'_s = hr_s * K_s  (K_s = prod_q hsum)

// ---------------- packed f32x2 helpers ----------------
__device__ __forceinline__ u64 pack2(float x, float y) {
    u64 r;
    asm("mov.b64 %0, {%1, %2};" : "=l"(r) : "f"(x), "f"(y));
    return r;
}
__device__ __forceinline__ void unpack2(u64 v, float &x, float &y) {
    asm("mov.b64 {%0, %1}, %2;" : "=f"(x), "=f"(y) : "l"(v));
}
__device__ __forceinline__ u64 fma2(u64 a, u64 b, u64 c) {
    u64 d;
    asm("fma.rn.f32x2 %0, %1, %2, %3;" : "=l"(d) : "l"(a), "l"(b), "l"(c));
    return d;
}
__device__ __forceinline__ u64 mul2(u64 a, u64 b) {
    u64 d;
    asm("mul.rn.f32x2 %0, %1, %2;" : "=l"(d) : "l"(a), "l"(b));
    return d;
}

// softplus(20x), overflow-safe (matches jax.nn.softplus = max(y,0)+log1p(exp(-|y|)))
__device__ __forceinline__ float sp20(float x) {
    float y = 20.0f * x;
    return fmaxf(y, 0.0f) + log1pf(expf(-fabsf(y)));
}

// ---------------- prep: heads + ratios (tiny) ----------------
__global__ void prep_kernel(const float* __restrict__ heads_param,
                            const float* __restrict__ hr_param,
                            float* __restrict__ out) {
    __shared__ float ssum[NS];
    __shared__ float stot;
    int s = threadIdx.x;            // 64 threads, s = head index
    if (s == 0) out[0] = 0.0f;      // d_out is poisoned; zero it every launch

    float K = 1.0f;
    for (int q = 0; q < NQ; q++) {
        const float* p = heads_param + (s * NQ + q) * NP;
        float a = sp20(p[0]);
        float b = sp20(p[1]);
        float c = sp20(p[2]);
        float sum = a + b + c;
        float E = fmaxf(sum, 1e-12f);     // reference eps clamp
        float hsum = sum / E;             // == 1.0 exactly unless sum < eps
        float inv = 1.0f / fmaxf(sum, 1e-30f);  // safe even if sum underflows to 0
        g_h0[q * NS + s] = a * inv;
        g_h1[q * NS + s] = b * inv;
        K *= hsum;
    }

    float v = sp20(hr_param[s]);
    ssum[s] = v;
    __syncthreads();
    if (s == 0) {
        float t = 0.0f;
        for (int i = 0; i < NS; i++) t += ssum[i];
        stot = fmaxf(t, 1e-12f);
    }
    __syncthreads();
    float r = v / stot;
    r = (r + 0.001f / 64.0f) / 1.001f;
    g_hr[s] = r * K;     // fold per-head hsum product into the ratio
}

// ---------------- main: coverage + variance loss ----------------
__global__ void __launch_bounds__(BN)
main_kernel(const float* __restrict__ pauli,
            const float* __restrict__ coeff,
            float* __restrict__ out, int N) {
    extern __shared__ float sh[];
    float* slab  = sh;                      // BN * 150 floats (pauli rows)
    float* sh_h0 = sh + BN * NQ * NP;       // 3200
    float* sh_h1 = sh_h0 + NQ * NS;         // 3200
    float* sh_hr = sh_h1 + NQ * NS;         // 64

    int tid   = threadIdx.x;
    int base  = blockIdx.x * BN;
    int count = min(BN, N - base);

    // Coalesced stage of this block's pauli rows
    int total = count * (NQ * NP);
    const float* src = pauli + (size_t)base * (NQ * NP);
    for (int i = tid; i < total; i += BN) slab[i] = src[i];
    // Heads into shared (broadcast-read later)
    for (int i = tid; i < NQ * NS; i += BN) {
        sh_h0[i] = g_h0[i];
        sh_h1[i] = g_h1[i];
    }
    if (tid < NS) sh_hr[tid] = g_hr[tid];
    __syncthreads();

    float term = 0.0f;
    if (tid < count) {
        const float* prow = slab + tid * (NQ * NP);
        u64 prod[NS / 2];
        #pragma unroll
        for (int i = 0; i < NS / 2; i++) prod[i] = 0x3F8000003F800000ULL;  // {1,1}

        #pragma unroll 2
        for (int q = 0; q < NQ; q++) {
            float p0 = prow[q * 3 + 0];
            float p1 = prow[q * 3 + 1];
            float p2 = prow[q * 3 + 2];
            float s0 = p0 - p2, s1 = p1 - p2;
            u64 d0 = pack2(s0, s0);
            u64 d1 = pack2(s1, s1);
            u64 pb = pack2(p2, p2);
            const u64* h0q = reinterpret_cast<const u64*>(sh_h0 + q * NS);
            const u64* h1q = reinterpret_cast<const u64*>(sh_h1 + q * NS);
            #pragma unroll
            for (int i = 0; i < NS / 2; i++) {
                u64 t = fma2(h1q[i], d1, pb);   // p2 + H1*(p1-p2)
                t = fma2(h0q[i], d0, t);        //    + H0*(p0-p2)
                prod[i] = mul2(prod[i], t);     // running product over q
            }
        }

        // cov = sum_s hr'_s * prod_s
        u64 acc = 0ULL;  // packed {0,0}
        const u64* hr2 = reinterpret_cast<const u64*>(sh_hr);
        #pragma unroll
        for (int i = 0; i < NS / 2; i++) acc = fma2(hr2[i], prod[i], acc);
        float cl, ch;
        unpack2(acc, cl, ch);
        float cov = cl + ch;

        float c = coeff[base + tid];
        term = (c * c) / cov;
    }

    // Block reduction (reuse slab after sync)
    __syncthreads();
    slab[tid] = term;
    __syncthreads();
    for (int off = BN / 2; off > 0; off >>= 1) {
        if (tid < off) slab[tid] += slab[tid + off];
        __syncthreads();
    }
    if (tid == 0) atomicAdd(out, slab[0]);
}

extern "C" void kernel_launch(void* const* d_in, const int* in_sizes, int n_in,
                              void* d_out, int out_size) {
    const float* pauli = (const float*)d_in[0];   // [N, 50, 3] f32
    const float* coeff = (const float*)d_in[1];   // [N] f32
    const float* hp    = (const float*)d_in[2];   // [64, 50, 3] f32
    const float* hrp   = (const float*)d_in[3];   // [64] f32
    float* out = (float*)d_out;
    int N = in_sizes[1];

    prep_kernel<<<1, NS>>>(hp, hrp, out);

    size_t shmem = (size_t)(BN * NQ * NP + 2 * NQ * NS + NS) * sizeof(float);
    cudaFuncSetAttribute(main_kernel, cudaFuncAttributeMaxDynamicSharedMemorySize,
                         (int)shmem);
    int nb = (N + BN - 1) / BN;
    main_kernel<<<nb, BN, shmem>>>(pauli, coeff, out, N);
}

// round 2
// speedup vs baseline: 1.1318x; 1.1318x over previous
#include <cuda_runtime.h>
#include <math.h>

#define NQ 50
#define NS 64
#define NP 3
#define BN 128          // n-rows per block
#define ROWSTRIDE 153   // padded slab row stride (odd mod 32 -> conflict-free)

typedef unsigned long long u64;

// Precomputed head tables (device globals: no allocation allowed)
// g_h01[q*32 + pair] = {H0[2p], H0[2p+1], H1[2p], H1[2p+1]}  (one LDS.128 per pair)
__device__ float4 g_h01[NQ * NS / 2];
__device__ float  g_hr[NS];          // hr'_s = hr_s * K_s  (K_s = prod_q hsum)

// ---------------- packed f32x2 helpers ----------------
__device__ __forceinline__ u64 pack2(float x, float y) {
    u64 r;
    asm("mov.b64 %0, {%1, %2};" : "=l"(r) : "f"(x), "f"(y));
    return r;
}
__device__ __forceinline__ void unpack2(u64 v, float &x, float &y) {
    asm("mov.b64 {%0, %1}, %2;" : "=f"(x), "=f"(y) : "l"(v));
}
__device__ __forceinline__ u64 fma2(u64 a, u64 b, u64 c) {
    u64 d;
    asm("fma.rn.f32x2 %0, %1, %2, %3;" : "=l"(d) : "l"(a), "l"(b), "l"(c));
    return d;
}
__device__ __forceinline__ u64 mul2(u64 a, u64 b) {
    u64 d;
    asm("mul.rn.f32x2 %0, %1, %2;" : "=l"(d) : "l"(a), "l"(b));
    return d;
}

// softplus(20x), overflow-safe (matches jax.nn.softplus = max(y,0)+log1p(exp(-|y|)))
__device__ __forceinline__ float sp20(float x) {
    float y = 20.0f * x;
    return fmaxf(y, 0.0f) + log1pf(expf(-fabsf(y)));
}

// ---------------- prep: heads + ratios (parallel over (s,q)) ----------------
__global__ void __launch_bounds__(512)
prep_kernel(const float* __restrict__ heads_param,
            const float* __restrict__ hr_param,
            float* __restrict__ out) {
    __shared__ float sh0[NQ][NS];
    __shared__ float sh1[NQ][NS];
    __shared__ float shK[8][NS];
    __shared__ float ssum[NS];

    int s  = threadIdx.x;   // 64
    int qt = threadIdx.y;   // 8
    int tid = s + NS * qt;

    if (tid == 0) out[0] = 0.0f;   // d_out is poisoned; zero it every launch

    float K = 1.0f;
    for (int q = qt; q < NQ; q += 8) {
        const float* p = heads_param + (s * NQ + q) * NP;
        float a = sp20(p[0]);
        float b = sp20(p[1]);
        float c = sp20(p[2]);
        float sum = a + b + c;
        float E = fmaxf(sum, 1e-12f);           // reference eps clamp
        float hsum = sum / E;                   // == 1.0 unless sum < eps
        float inv = 1.0f / fmaxf(sum, 1e-30f);  // safe if sum underflows to 0
        sh0[q][s] = a * inv;
        sh1[q][s] = b * inv;
        K *= hsum;
    }
    shK[qt][s] = K;
    if (qt == 0) ssum[s] = sp20(hr_param[s]);
    __syncthreads();

    if (qt == 0) {
        float Ks = 1.0f;
        #pragma unroll
        for (int i = 0; i < 8; i++) Ks *= shK[i][s];
        float tot = 0.0f;
        #pragma unroll
        for (int i = 0; i < NS; i++) tot += ssum[i];   // redundant per-thread, cheap
        tot = fmaxf(tot, 1e-12f);
        float r = ssum[s] / tot;
        r = (r + 0.001f / 64.0f) / 1.001f;
        g_hr[s] = r * Ks;                        // fold per-head hsum product in
    }

    // pack h01 table: {H0 pair, H1 pair} per 16 bytes
    for (int i = tid; i < NQ * NS / 2; i += 512) {
        int q = i >> 5;
        int pr = i & 31;
        g_h01[i] = make_float4(sh0[q][2 * pr], sh0[q][2 * pr + 1],
                               sh1[q][2 * pr], sh1[q][2 * pr + 1]);
    }
}

// ---------------- main: coverage + variance loss ----------------
__global__ void __launch_bounds__(BN)
main_kernel(const float* __restrict__ pauli,
            const float* __restrict__ coeff,
            float* __restrict__ out, int N) {
    extern __shared__ float sh[];
    // layout: h01 (16B aligned, 25600B) | hr (256B) | slab (BN*ROWSTRIDE floats)
    float*  sh_h01f = sh;
    float*  sh_hr   = sh + NQ * NS * 2;            // 6400 floats in
    float*  slab    = sh_hr + NS;

    int tid   = threadIdx.x;
    int base  = blockIdx.x * BN;
    int count = min(BN, N - base);

    // Stage heads (coalesced float4) and ratios
    {
        const float4* src4 = (const float4*)g_h01;
        float4* dst4 = (float4*)sh_h01f;
        for (int i = tid; i < NQ * NS / 2; i += BN) dst4[i] = src4[i];
        if (tid < NS) sh_hr[tid] = g_hr[tid];
    }
    // Coalesced stage of this block's pauli rows into padded slab
    {
        const float* src = pauli + (size_t)base * (NQ * NP);
        int total = count * (NQ * NP);
        for (int i = tid; i < total; i += BN) {
            int r = i / (NQ * NP);
            int c = i - r * (NQ * NP);
            slab[r * ROWSTRIDE + c] = src[i];
        }
    }
    __syncthreads();

    float term = 0.0f;
    if (tid < count) {
        const float* prow = slab + tid * ROWSTRIDE;
        u64 prod[NS / 2];
        #pragma unroll
        for (int i = 0; i < NS / 2; i++) prod[i] = 0x3F8000003F800000ULL;  // {1,1}

        #pragma unroll 2
        for (int q = 0; q < NQ; q++) {
            float p0 = prow[q * 3 + 0];
            float p1 = prow[q * 3 + 1];
            float p2 = prow[q * 3 + 2];
            float s0 = p0 - p2, s1 = p1 - p2;
            u64 d0 = pack2(s0, s0);
            u64 d1 = pack2(s1, s1);
            u64 pb = pack2(p2, p2);
            const double2* hq = (const double2*)(sh_h01f + q * NS * 2);
            #pragma unroll
            for (int i = 0; i < NS / 2; i++) {
                double2 h = hq[i];                       // one LDS.128
                u64 h0 = __double_as_longlong(h.x);      // free reg alias
                u64 h1 = __double_as_longlong(h.y);
                u64 t = fma2(h1, d1, pb);    // p2 + H1*(p1-p2)
                t = fma2(h0, d0, t);         //    + H0*(p0-p2)
                prod[i] = mul2(prod[i], t);  // running product over q
            }
        }

        // cov = sum_s hr'_s * prod_s
        u64 acc = 0ULL;  // packed {0,0}
        const u64* hr2 = (const u64*)sh_hr;
        #pragma unroll
        for (int i = 0; i < NS / 2; i++) acc = fma2(hr2[i], prod[i], acc);
        float cl, ch;
        unpack2(acc, cl, ch);
        float cov = cl + ch;

        float c = coeff[base + tid];
        term = (c * c) / cov;
    }

    // Block reduction (reuse slab after sync)
    __syncthreads();
    slab[tid] = term;
    __syncthreads();
    for (int off = BN / 2; off > 0; off >>= 1) {
        if (tid < off) slab[tid] += slab[tid + off];
        __syncthreads();
    }
    if (tid == 0) atomicAdd(out, slab[0]);
}

extern "C" void kernel_launch(void* const* d_in, const int* in_sizes, int n_in,
                              void* d_out, int out_size) {
    const float* pauli = (const float*)d_in[0];   // [N, 50, 3] f32
    const float* coeff = (const float*)d_in[1];   // [N] f32
    const float* hp    = (const float*)d_in[2];   // [64, 50, 3] f32
    const float* hrp   = (const float*)d_in[3];   // [64] f32
    float* out = (float*)d_out;
    int N = in_sizes[1];

    prep_kernel<<<1, dim3(NS, 8)>>>(hp, hrp, out);

    size_t shmem = (size_t)(NQ * NS * 2 + NS + BN * ROWSTRIDE) * sizeof(float);
    cudaFuncSetAttribute(main_kernel, cudaFuncAttributeMaxDynamicSharedMemorySize,
                         (int)shmem);
    int nb = (N + BN - 1) / BN;
    main_kernel<<<nb, BN, shmem>>>(pauli, coeff, out, N);
}

// round 3
// speedup vs baseline: 1.2002x; 1.0604x over previous
#include <cuda_runtime.h>
#include <math.h>

#define NQ 50
#define NS 64
#define NP 3
#define BN 128          // threads per block == words per tile
#define CH 10           // qubits per chunk
#define NCHUNK 5
#define SROW 31         // slab row stride (odd -> conflict-free)

typedef unsigned long long u64;

// Precomputed head tables (device globals: no allocation allowed)
// g_h01[q*32 + pair] = {H0[2p], H0[2p+1], H1[2p], H1[2p+1]}
__device__ float4 g_h01[NQ * NS / 2];
__device__ float  g_hr[NS];          // hr'_s = hr_s * K_s

// ---------------- packed f32x2 helpers ----------------
__device__ __forceinline__ u64 pack2(float x, float y) {
    u64 r;
    asm("mov.b64 %0, {%1, %2};" : "=l"(r) : "f"(x), "f"(y));
    return r;
}
__device__ __forceinline__ void unpack2(u64 v, float &x, float &y) {
    asm("mov.b64 {%0, %1}, %2;" : "=f"(x), "=f"(y) : "l"(v));
}
__device__ __forceinline__ u64 fma2(u64 a, u64 b, u64 c) {
    u64 d;
    asm("fma.rn.f32x2 %0, %1, %2, %3;" : "=l"(d) : "l"(a), "l"(b), "l"(c));
    return d;
}
__device__ __forceinline__ u64 mul2(u64 a, u64 b) {
    u64 d;
    asm("mul.rn.f32x2 %0, %1, %2;" : "=l"(d) : "l"(a), "l"(b));
    return d;
}

// softplus(20x), overflow-safe
__device__ __forceinline__ float sp20(float x) {
    float y = 20.0f * x;
    return fmaxf(y, 0.0f) + log1pf(expf(-fabsf(y)));
}

// ---------------- prep: heads + ratios ----------------
__global__ void __launch_bounds__(512)
prep_kernel(const float* __restrict__ heads_param,
            const float* __restrict__ hr_param,
            float* __restrict__ out) {
    __shared__ float sh0[NQ][NS];
    __shared__ float sh1[NQ][NS];
    __shared__ float shK[8][NS];
    __shared__ float ssum[NS];

    int s  = threadIdx.x;   // 64
    int qt = threadIdx.y;   // 8
    int tid = s + NS * qt;

    if (tid == 0) out[0] = 0.0f;   // d_out is poisoned; zero every launch

    float K = 1.0f;
    for (int q = qt; q < NQ; q += 8) {
        const float* p = heads_param + (s * NQ + q) * NP;
        float a = sp20(p[0]);
        float b = sp20(p[1]);
        float c = sp20(p[2]);
        float sum = a + b + c;
        float E = fmaxf(sum, 1e-12f);
        float hsum = sum / E;                   // == 1.0 unless sum < eps
        float inv = 1.0f / fmaxf(sum, 1e-30f);
        sh0[q][s] = a * inv;
        sh1[q][s] = b * inv;
        K *= hsum;
    }
    shK[qt][s] = K;
    if (qt == 0) ssum[s] = sp20(hr_param[s]);
    __syncthreads();

    if (qt == 0) {
        float Ks = 1.0f;
        #pragma unroll
        for (int i = 0; i < 8; i++) Ks *= shK[i][s];
        float tot = 0.0f;
        #pragma unroll
        for (int i = 0; i < NS; i++) tot += ssum[i];
        tot = fmaxf(tot, 1e-12f);
        float r = ssum[s] / tot;
        r = (r + 0.001f / 64.0f) / 1.001f;
        g_hr[s] = r * Ks;
    }

    for (int i = tid; i < NQ * NS / 2; i += 512) {
        int q = i >> 5;
        int pr = i & 31;
        g_h01[i] = make_float4(sh0[q][2 * pr], sh0[q][2 * pr + 1],
                               sh1[q][2 * pr], sh1[q][2 * pr + 1]);
    }
}

// ---------------- main ----------------
__global__ void __launch_bounds__(BN, 4)
main_kernel(const float* __restrict__ pauli,
            const float* __restrict__ coeff,
            float* __restrict__ out, int N) {
    __shared__ __align__(16) float4 sh_h[NQ * 32];          // 25600 B
    __shared__ __align__(16) float  sh_hr[NS];              // 256 B
    __shared__ __align__(16) float  slab[BN * SROW];        // 15872 B
    __shared__ float ph[BN][2];                             // 1024 B
    __shared__ float red[4];

    int tid  = threadIdx.x;
    int wid  = tid >> 5;
    int lane = tid & 31;
    int half = wid >> 1;       // which 32 heads (uniform per warp)
    int wp   = wid & 1;
    int wl   = wp * 32 + lane; // first local word; second is wl+64

    int base  = blockIdx.x * BN;
    int count = min(BN, N - base);

    // Stage heads + ratios once per CTA
    for (int i = tid; i < NQ * 32; i += BN) sh_h[i] = g_h01[i];
    if (tid < NS) sh_hr[tid] = g_hr[tid];

    u64 prod[32];
    #pragma unroll
    for (int i = 0; i < 32; i++) prod[i] = 0x3F8000003F800000ULL;  // {1,1}

    for (int ch = 0; ch < NCHUNK; ch++) {
        __syncthreads();     // protect slab reuse
        int q0 = ch * CH;
        {   // coalesced stage of 30 floats per word for this chunk
            const float* src = pauli + (size_t)base * (NQ * NP) + q0 * NP;
            int total = count * (CH * NP);
            for (int i = tid; i < total; i += BN) {
                int r = i / (CH * NP);
                int c = i - r * (CH * NP);
                slab[r * SROW + c] = src[(size_t)r * (NQ * NP) + c];
            }
        }
        __syncthreads();

        const float* prowA = slab + wl * SROW;
        const float* prowB = slab + (wl + 64) * SROW;
        const double2* hbase = (const double2*)sh_h;

        #pragma unroll 2
        for (int qq = 0; qq < CH; qq++) {
            int q = q0 + qq;
            float a0 = prowA[qq * 3 + 0], a1 = prowA[qq * 3 + 1], a2 = prowA[qq * 3 + 2];
            float b0 = prowB[qq * 3 + 0], b1 = prowB[qq * 3 + 1], b2 = prowB[qq * 3 + 2];
            u64 da0 = pack2(a0 - a2, a0 - a2);
            u64 da1 = pack2(a1 - a2, a1 - a2);
            u64 pa  = pack2(a2, a2);
            u64 db0 = pack2(b0 - b2, b0 - b2);
            u64 db1 = pack2(b1 - b2, b1 - b2);
            u64 pb  = pack2(b2, b2);
            const double2* hq = hbase + q * 32 + half * 16;
            #pragma unroll
            for (int i = 0; i < 16; i++) {
                double2 h = hq[i];                      // one broadcast LDS.128
                u64 h0 = __double_as_longlong(h.x);
                u64 h1 = __double_as_longlong(h.y);
                u64 t = fma2(h1, da1, pa);
                t = fma2(h0, da0, t);
                prod[i] = mul2(prod[i], t);
                u64 u = fma2(h1, db1, pb);
                u = fma2(h0, db0, u);
                prod[16 + i] = mul2(prod[16 + i], u);
            }
        }
    }

    // partial cov over this thread's 32 heads, both words
    u64 accA = 0ULL, accB = 0ULL;
    const u64* hr2 = (const u64*)sh_hr + half * 16;
    #pragma unroll
    for (int i = 0; i < 16; i++) {
        accA = fma2(hr2[i], prod[i], accA);
        accB = fma2(hr2[i], prod[16 + i], accB);
    }
    float xl, xh;
    unpack2(accA, xl, xh);
    float covA = xl + xh;
    unpack2(accB, xl, xh);
    float covB = xl + xh;

    ph[wl][half]      = covA;
    ph[wl + 64][half] = covB;
    __syncthreads();

    float term = 0.0f;
    int w = base + tid;
    if (tid < count) {
        float cov = ph[tid][0] + ph[tid][1];
        float c = coeff[w];
        term = (c * c) / cov;
    }

    // warp reduce + cross-warp
    #pragma unroll
    for (int off = 16; off > 0; off >>= 1)
        term += __shfl_down_sync(0xFFFFFFFFu, term, off);
    if (lane == 0) red[wid] = term;
    __syncthreads();
    if (tid == 0) {
        float t = red[0] + red[1] + red[2] + red[3];
        atomicAdd(out, t);
    }
}

extern "C" void kernel_launch(void* const* d_in, const int* in_sizes, int n_in,
                              void* d_out, int out_size) {
    const float* pauli = (const float*)d_in[0];   // [N, 50, 3] f32
    const float* coeff = (const float*)d_in[1];   // [N] f32
    const float* hp    = (const float*)d_in[2];   // [64, 50, 3] f32
    const float* hrp   = (const float*)d_in[3];   // [64] f32
    float* out = (float*)d_out;
    int N = in_sizes[1];

    prep_kernel<<<1, dim3(NS, 8)>>>(hp, hrp, out);

    int nb = (N + BN - 1) / BN;
    main_kernel<<<nb, BN>>>(pauli, coeff, out, N);
}